// round 5
// baseline (speedup 1.0000x reference)
#include <cuda_runtime.h>
#include <math.h>

// Problem constants
#define B      1024
#define D      512
#define C      100000
#define TILE   128
#define KC     16
#define NT     ((C + TILE - 1) / TILE)   // 782 class tiles
#define SCALE_F 64.0f

// ArcFace margin constants (margin = 0.5)
#define COS_M  0.8775825618903728f
#define SIN_M  0.47942553860420301f
#define TH_M  (-0.8775825618903728f)
#define MM_M   0.23971276930210151f

// Scratch (no allocations allowed -> __device__ globals)
__device__ float g_einv[B];
__device__ float g_winv[C];
__device__ float g_ldot[B];
__device__ float g_pmax[NT * B];
__device__ float g_psum[NT * B];

// ---------------------------------------------------------------------------
// Inverse L2 norms of embedding rows (1024 x 512). One warp per row.
// ---------------------------------------------------------------------------
__global__ void e_norm_kernel(const float* __restrict__ E) {
    int warp = (blockIdx.x * blockDim.x + threadIdx.x) >> 5;
    int lane = threadIdx.x & 31;
    if (warp >= B) return;
    const float* row = E + (size_t)warp * D;
    float ss = 0.f;
    #pragma unroll
    for (int i = 0; i < D / 32; i++) {
        float v = row[lane + i * 32];
        ss = fmaf(v, v, ss);
    }
    #pragma unroll
    for (int o = 16; o > 0; o >>= 1) ss += __shfl_xor_sync(0xffffffffu, ss, o);
    if (lane == 0) g_einv[warp] = 1.0f / fmaxf(sqrtf(ss), 1e-12f);
}

// ---------------------------------------------------------------------------
// Inverse L2 norms of weight rows (100000 x 512). One warp per row.
// ---------------------------------------------------------------------------
__global__ void w_norm_kernel(const float* __restrict__ W) {
    int warp = (blockIdx.x * blockDim.x + threadIdx.x) >> 5;
    int lane = threadIdx.x & 31;
    if (warp >= C) return;
    const float* row = W + (size_t)warp * D;
    float ss = 0.f;
    #pragma unroll
    for (int i = 0; i < D / 32; i++) {
        float v = row[lane + i * 32];
        ss = fmaf(v, v, ss);
    }
    #pragma unroll
    for (int o = 16; o > 0; o >>= 1) ss += __shfl_xor_sync(0xffffffffu, ss, o);
    if (lane == 0) g_winv[warp] = 1.0f / fmaxf(sqrtf(ss), 1e-12f);
}

// ---------------------------------------------------------------------------
// Raw dot(e_b, w_label[b]) for each row. One warp per row.
// NOTE: labels are int32 (harness contract), not int64.
// ---------------------------------------------------------------------------
__global__ void label_dot_kernel(const float* __restrict__ E,
                                 const float* __restrict__ W,
                                 const int* __restrict__ labels) {
    int warp = (blockIdx.x * blockDim.x + threadIdx.x) >> 5;
    int lane = threadIdx.x & 31;
    if (warp >= B) return;
    int lab = labels[warp];
    const float* e = E + (size_t)warp * D;
    const float* w = W + (size_t)lab * D;
    float s = 0.f;
    #pragma unroll
    for (int i = 0; i < D / 32; i++) {
        s = fmaf(e[lane + i * 32], w[lane + i * 32], s);
    }
    #pragma unroll
    for (int o = 16; o > 0; o >>= 1) s += __shfl_xor_sync(0xffffffffu, s, o);
    if (lane == 0) g_ldot[warp] = s;
}

// ---------------------------------------------------------------------------
// Main: 128x128 tile GEMM (raw dot products) + fused per-tile online-softmax
// partials. grid = (8 row tiles, 782 class tiles); blocks with the same class
// tile are adjacent in launch order so the weight tile is read from HBM once
// and hit in L2 by the other 7 row tiles.
// ---------------------------------------------------------------------------
__global__ void __launch_bounds__(256)
gemm_softmax_kernel(const float* __restrict__ E, const float* __restrict__ W) {
    const int rowTile   = blockIdx.x;      // 0..7
    const int classTile = blockIdx.y;      // 0..NT-1
    const int rowBase   = rowTile * TILE;
    const int classBase = classTile * TILE;

    __shared__ float As[KC][TILE];
    __shared__ float Bs[KC][TILE];

    const int t  = threadIdx.x;
    const int tx = t & 15;     // class sub-tile
    const int ty = t >> 4;     // row sub-tile

    float acc[8][8];
    #pragma unroll
    for (int i = 0; i < 8; i++)
        #pragma unroll
        for (int j = 0; j < 8; j++) acc[i][j] = 0.f;

    // Loader mapping: thread loads 8 consecutive k-floats of one tile row.
    const int lr = t >> 1;            // tile row 0..127
    const int lk = (t & 1) * 8;       // k offset 0 or 8

    const float* Eg = E + (size_t)(rowBase + lr) * D + lk;
    const int    wc = classBase + lr;
    const bool   wvalid = (wc < C);
    const float* Wg = W + (size_t)(wvalid ? wc : 0) * D + lk;

    for (int k0 = 0; k0 < D; k0 += KC) {
        float4 a0 = *(const float4*)(Eg + k0);
        float4 a1 = *(const float4*)(Eg + k0 + 4);
        float4 b0 = make_float4(0.f, 0.f, 0.f, 0.f);
        float4 b1 = make_float4(0.f, 0.f, 0.f, 0.f);
        if (wvalid) {
            b0 = *(const float4*)(Wg + k0);
            b1 = *(const float4*)(Wg + k0 + 4);
        }
        __syncthreads();   // previous compute finished reading smem
        As[lk + 0][lr] = a0.x; As[lk + 1][lr] = a0.y;
        As[lk + 2][lr] = a0.z; As[lk + 3][lr] = a0.w;
        As[lk + 4][lr] = a1.x; As[lk + 5][lr] = a1.y;
        As[lk + 6][lr] = a1.z; As[lk + 7][lr] = a1.w;
        Bs[lk + 0][lr] = b0.x; Bs[lk + 1][lr] = b0.y;
        Bs[lk + 2][lr] = b0.z; Bs[lk + 3][lr] = b0.w;
        Bs[lk + 4][lr] = b1.x; Bs[lk + 5][lr] = b1.y;
        Bs[lk + 6][lr] = b1.z; Bs[lk + 7][lr] = b1.w;
        __syncthreads();

        #pragma unroll
        for (int kk = 0; kk < KC; kk++) {
            float4 av0 = *(const float4*)&As[kk][ty * 8];
            float4 av1 = *(const float4*)&As[kk][ty * 8 + 4];
            float4 bv0 = *(const float4*)&Bs[kk][tx * 8];
            float4 bv1 = *(const float4*)&Bs[kk][tx * 8 + 4];
            float a[8] = {av0.x, av0.y, av0.z, av0.w, av1.x, av1.y, av1.z, av1.w};
            float b[8] = {bv0.x, bv0.y, bv0.z, bv0.w, bv1.x, bv1.y, bv1.z, bv1.w};
            #pragma unroll
            for (int i = 0; i < 8; i++)
                #pragma unroll
                for (int j = 0; j < 8; j++)
                    acc[i][j] = fmaf(a[i], b[j], acc[i][j]);
        }
    }

    // Epilogue: cosine -> logits -> per-tile per-row (max, sumexp)
    float einv_r[8], winv_c[8];
    bool  val[8];
    #pragma unroll
    for (int i = 0; i < 8; i++) einv_r[i] = g_einv[rowBase + ty * 8 + i];
    #pragma unroll
    for (int j = 0; j < 8; j++) {
        int c = classBase + tx * 8 + j;
        val[j]    = (c < C);
        winv_c[j] = val[j] ? g_winv[c] : 0.f;
    }

    #pragma unroll
    for (int i = 0; i < 8; i++) {
        float lg[8];
        float m = -INFINITY;
        #pragma unroll
        for (int j = 0; j < 8; j++) {
            lg[j] = val[j] ? (SCALE_F * acc[i][j] * einv_r[i] * winv_c[j])
                           : -INFINITY;
            m = fmaxf(m, lg[j]);
        }
        // reduce across the 16 tx-threads (contiguous 16-lane group)
        #pragma unroll
        for (int o = 1; o < 16; o <<= 1)
            m = fmaxf(m, __shfl_xor_sync(0xffffffffu, m, o));
        float s = 0.f;
        #pragma unroll
        for (int j = 0; j < 8; j++) s += expf(lg[j] - m);   // exp(-inf)=0 for oob
        #pragma unroll
        for (int o = 1; o < 16; o <<= 1)
            s += __shfl_xor_sync(0xffffffffu, s, o);
        if (tx == 0) {
            int b = rowBase + ty * 8 + i;
            g_pmax[classTile * B + b] = m;
            g_psum[classTile * B + b] = s;
        }
    }
}

// ---------------------------------------------------------------------------
// Finalize: merge NT partials per row, apply margin correction at the label,
// compute NLL, block-reduce mean. One block of 1024 threads (thread = row).
// NOTE: labels are int32 (harness contract), not int64.
// ---------------------------------------------------------------------------
__global__ void finalize_kernel(const int* __restrict__ labels,
                                float* __restrict__ out) {
    const int b = threadIdx.x;
    float m = -INFINITY, s = 0.f;
    for (int t2 = 0; t2 < NT; t2++) {
        float mt = g_pmax[t2 * B + b];
        float st = g_psum[t2 * B + b];
        if (mt > m) { s = s * expf(m - mt) + st; m = mt; }
        else        { s += st * expf(mt - m); }
    }

    int lab = labels[b];
    float cosl = g_ldot[b] * g_einv[b] * g_winv[lab];
    float c2   = 1.0f - cosl * cosl;
    float sine = sqrtf(fminf(fmaxf(c2, 0.f), 1.f));
    float phi  = cosl * COS_M - sine * SIN_M;
    phi = (cosl > TH_M) ? phi : (cosl - MM_M);

    float lo = SCALE_F * cosl;    // original logit at the label
    float ln = SCALE_F * phi;     // margined logit (ln <= lo <= m always)
    s += expf(ln - m) - expf(lo - m);

    float nll = m + logf(s) - ln;

    __shared__ float red[B];
    red[b] = nll;
    __syncthreads();
    #pragma unroll
    for (int o = B / 2; o > 0; o >>= 1) {
        if (b < o) red[b] += red[b + o];
        __syncthreads();
    }
    if (b == 0) out[0] = red[0] / (float)B;
}

// ---------------------------------------------------------------------------
extern "C" void kernel_launch(void* const* d_in, const int* in_sizes, int n_in,
                              void* d_out, int out_size) {
    const float* E      = (const float*)d_in[0];
    const float* W      = (const float*)d_in[1];
    const int*   labels = (const int*)d_in[2];
    float*       out    = (float*)d_out;

    e_norm_kernel<<<(B * 32) / 256, 256>>>(E);
    w_norm_kernel<<<(C * 32 + 255) / 256, 256>>>(W);
    label_dot_kernel<<<(B * 32) / 256, 256>>>(E, W, labels);

    dim3 grid(B / TILE, NT);   // (8, 782); x-major order => weight-tile L2 reuse
    gemm_softmax_kernel<<<grid, 256>>>(E, W);

    finalize_kernel<<<1, B>>>(labels, out);
}

// round 8
// speedup vs baseline: 3.9051x; 3.9051x over previous
#include <cuda_runtime.h>
#include <math.h>
#include <stdint.h>

// ---------------------------------------------------------------------------
// Problem constants
// ---------------------------------------------------------------------------
#define B       1024
#define D       512
#define C       100000
#define TM      128                    // CTA rows
#define TN      128                    // CTA classes
#define NT      ((C + TN - 1) / TN)    // 782 class tiles
#define NTE     (NT * 2)               // 2 col-half partials per class tile
#define KCHUNK  32                     // K elems per pipeline chunk
#define NCHUNK  (D / KCHUNK)           // 16
#define SCALE_F 64.0f

// ArcFace margin constants (margin = 0.5)
#define COS_M  0.8775825618903728f
#define SIN_M  0.47942553860420301f
#define TH_M  (-0.8775825618903728f)
#define MM_M   0.23971276930210151f

// smem tile geometry: padded stride 36 floats -> conflict-free fragment loads
#define TSTRIDE     36
#define TILE_BYTES  (TM * TSTRIDE * 4)     // 18432
#define STAGE_BYTES (2 * TILE_BYTES)       // 36864 (A then B)
#define SMEM_BYTES  (512 + 3 * STAGE_BYTES)

// Scratch (__device__ globals; no allocations allowed)
__device__ float g_einv[B];
__device__ float g_winv[C];
__device__ float g_ldot[B];
__device__ float g_pmax[(size_t)B * NTE];
__device__ float g_psum[(size_t)B * NTE];
__device__ float g_nll[B];

// ---------------------------------------------------------------------------
// PTX helpers (base ISA only -- nothing gated on sm_103a)
// ---------------------------------------------------------------------------
__device__ __forceinline__ uint32_t smem_u32(const void* p) {
    uint32_t a;
    asm("{ .reg .u64 t; cvta.to.shared.u64 t, %1; cvt.u32.u64 %0, t; }"
        : "=r"(a) : "l"(p));
    return a;
}

__device__ __forceinline__ void cp16(uint32_t dst, const void* src) {
    asm volatile("cp.async.cg.shared.global [%0], [%1], 16;"
                 :: "r"(dst), "l"(src));
}
__device__ __forceinline__ void cp_commit() {
    asm volatile("cp.async.commit_group;" ::: "memory");
}
template <int N> __device__ __forceinline__ void cp_wait() {
    asm volatile("cp.async.wait_group %0;" :: "n"(N) : "memory");
}

// m16n8k8 tf32 mma; acc in-place
__device__ __forceinline__ void mma_tf32(float* d, const uint32_t* a,
                                         const uint32_t* b) {
    asm volatile(
        "mma.sync.aligned.m16n8k8.row.col.f32.tf32.tf32.f32 "
        "{%0,%1,%2,%3}, {%4,%5,%6,%7}, {%8,%9}, {%0,%1,%2,%3};"
        : "+f"(d[0]), "+f"(d[1]), "+f"(d[2]), "+f"(d[3])
        : "r"(a[0]), "r"(a[1]), "r"(a[2]), "r"(a[3]), "r"(b[0]), "r"(b[1]));
}

// ---------------------------------------------------------------------------
// Norm / label-dot kernels (one warp per row)
// ---------------------------------------------------------------------------
__global__ void e_norm_kernel(const float* __restrict__ E) {
    int warp = (blockIdx.x * blockDim.x + threadIdx.x) >> 5;
    int lane = threadIdx.x & 31;
    if (warp >= B) return;
    const float* row = E + (size_t)warp * D;
    float ss = 0.f;
    #pragma unroll
    for (int i = 0; i < D / 32; i++) { float v = row[lane + i * 32]; ss = fmaf(v, v, ss); }
    #pragma unroll
    for (int o = 16; o > 0; o >>= 1) ss += __shfl_xor_sync(0xffffffffu, ss, o);
    if (lane == 0) g_einv[warp] = 1.0f / fmaxf(sqrtf(ss), 1e-12f);
}

__global__ void w_norm_kernel(const float* __restrict__ W) {
    int warp = (blockIdx.x * blockDim.x + threadIdx.x) >> 5;
    int lane = threadIdx.x & 31;
    if (warp >= C) return;
    const float* row = W + (size_t)warp * D;
    float ss = 0.f;
    #pragma unroll
    for (int i = 0; i < D / 32; i++) { float v = row[lane + i * 32]; ss = fmaf(v, v, ss); }
    #pragma unroll
    for (int o = 16; o > 0; o >>= 1) ss += __shfl_xor_sync(0xffffffffu, ss, o);
    if (lane == 0) g_winv[warp] = 1.0f / fmaxf(sqrtf(ss), 1e-12f);
}

__global__ void label_dot_kernel(const float* __restrict__ E,
                                 const float* __restrict__ W,
                                 const int* __restrict__ labels) {
    int warp = (blockIdx.x * blockDim.x + threadIdx.x) >> 5;
    int lane = threadIdx.x & 31;
    if (warp >= B) return;
    int lab = labels[warp];
    const float* e = E + (size_t)warp * D;
    const float* w = W + (size_t)lab * D;
    float s = 0.f;
    #pragma unroll
    for (int i = 0; i < D / 32; i++) s = fmaf(e[lane + i * 32], w[lane + i * 32], s);
    #pragma unroll
    for (int o = 16; o > 0; o >>= 1) s += __shfl_xor_sync(0xffffffffu, s, o);
    if (lane == 0) g_ldot[warp] = s;
}

// ---------------------------------------------------------------------------
// Main: tf32 mma.sync GEMM (128x128 CTA tile, 4 warps of 64x64) + fused
// per-tile softmax partials. grid (8, 782) x-major: the 8 rowTiles of one
// classTile are launch-adjacent so the W tile is HBM-read once, L2-hit 7x.
// ---------------------------------------------------------------------------
__global__ void __launch_bounds__(128, 2)
gemm_tc_kernel(const float* __restrict__ E, const float* __restrict__ W) {
    extern __shared__ float smem[];
    float* winv_s = smem;              // 128 floats
    float* stage0 = smem + 128;        // 3 stages of (A tile | B tile)

    const int tid  = threadIdx.x;
    const int wid  = tid >> 5;
    const int lane = tid & 31;
    const int wm   = wid >> 1;         // warp row-half   (0..1)
    const int wn   = wid & 1;          // warp class-half (0..1)
    const int qid  = lane >> 2;        // 0..7
    const int ql   = lane & 3;         // 0..3
    const int rowBase   = blockIdx.x * TM;
    const int classBase = blockIdx.y * TN;

    winv_s[tid] = (classBase + tid < C) ? g_winv[classBase + tid] : 0.0f;

    float acc[4][8][4];
    #pragma unroll
    for (int mt = 0; mt < 4; mt++)
        #pragma unroll
        for (int nt = 0; nt < 8; nt++)
            #pragma unroll
            for (int c = 0; c < 4; c++) acc[mt][nt][c] = 0.f;

    const uint32_t s0 = smem_u32(stage0);

    // --- chunk loader: 32KB (A 16KB + B 16KB) into padded+strided smem ---
    auto load_chunk = [&](int k, int st) {
        const uint32_t sa  = s0 + st * STAGE_BYTES;
        const uint32_t sb  = sa + TILE_BYTES;
        const int      kof = k * KCHUNK;
        const float*   Ep  = E + (size_t)rowBase * D + kof;
        #pragma unroll
        for (int i = 0; i < 8; i++) {
            int idx = tid + i * 128;      // 0..1023
            int r = idx >> 3, c = idx & 7;
            cp16(sa + r * (TSTRIDE * 4) + c * 16, Ep + (size_t)r * D + c * 4);
        }
        #pragma unroll
        for (int i = 0; i < 8; i++) {
            int idx = tid + i * 128;
            int r = idx >> 3, c = idx & 7;
            int cls = classBase + r;
            if (cls < C)
                cp16(sb + r * (TSTRIDE * 4) + c * 16,
                     W + (size_t)cls * D + kof + c * 4);
        }
        cp_commit();
    };

    auto compute_chunk = [&](int st) {
        const float* As = stage0 + st * (STAGE_BYTES / 4);
        const float* Bs = As + TILE_BYTES / 4;
        #pragma unroll
        for (int ks = 0; ks < 4; ks++) {
            const int k0 = ks * 8 + ql;
            uint32_t a[4][4], b[8][2];
            #pragma unroll
            for (int mt = 0; mt < 4; mt++) {
                const float* ap = As + (wm * 64 + mt * 16 + qid) * TSTRIDE + k0;
                a[mt][0] = __float_as_uint(ap[0]);
                a[mt][1] = __float_as_uint(ap[8 * TSTRIDE]);
                a[mt][2] = __float_as_uint(ap[4]);
                a[mt][3] = __float_as_uint(ap[8 * TSTRIDE + 4]);
            }
            #pragma unroll
            for (int nt = 0; nt < 8; nt++) {
                const float* bp = Bs + (wn * 64 + nt * 8 + qid) * TSTRIDE + k0;
                b[nt][0] = __float_as_uint(bp[0]);
                b[nt][1] = __float_as_uint(bp[4]);
            }
            #pragma unroll
            for (int mt = 0; mt < 4; mt++)
                #pragma unroll
                for (int nt = 0; nt < 8; nt++)
                    mma_tf32(acc[mt][nt], a[mt], b[nt]);
        }
    };

    load_chunk(0, 0);
    load_chunk(1, 1);
    load_chunk(2, 2);

    for (int k = 0; k < NCHUNK; k++) {
        const int st = k % 3;
        if (k < NCHUNK - 2)       cp_wait<2>();
        else if (k == NCHUNK - 2) cp_wait<1>();
        else                      cp_wait<0>();
        __syncthreads();
        compute_chunk(st);
        if (k + 3 < NCHUNK) {
            __syncthreads();              // all warps done reading stage st
            load_chunk(k + 3, st);
        }
    }

    // --- epilogue: logits + per-(row, 64-col-half) online softmax partial ---
    const int tileIdx = blockIdx.y * 2 + wn;
    #pragma unroll
    for (int mt = 0; mt < 4; mt++) {
        #pragma unroll
        for (int h = 0; h < 2; h++) {
            const int   row  = rowBase + wm * 64 + mt * 16 + qid + h * 8;
            const float einv = g_einv[row];
            float lg[16];
            float m = -INFINITY;
            #pragma unroll
            for (int nt = 0; nt < 8; nt++) {
                #pragma unroll
                for (int c = 0; c < 2; c++) {
                    float wv = winv_s[wn * 64 + nt * 8 + ql * 2 + c];
                    float v  = acc[mt][nt][h * 2 + c];
                    float l  = (wv > 0.f) ? (SCALE_F * v * einv * wv) : -INFINITY;
                    lg[nt * 2 + c] = l;
                    m = fmaxf(m, l);
                }
            }
            m = fmaxf(m, __shfl_xor_sync(0xffffffffu, m, 1));
            m = fmaxf(m, __shfl_xor_sync(0xffffffffu, m, 2));
            float s = 0.f;
            if (m > -INFINITY) {
                #pragma unroll
                for (int j = 0; j < 16; j++) s += __expf(lg[j] - m);
            }
            s += __shfl_xor_sync(0xffffffffu, s, 1);
            s += __shfl_xor_sync(0xffffffffu, s, 2);
            if (ql == 0) {
                g_pmax[(size_t)row * NTE + tileIdx] = m;
                g_psum[(size_t)row * NTE + tileIdx] = s;
            }
        }
    }
}

// ---------------------------------------------------------------------------
// Finalize stage 1: one warp per row merges NTE partials + label correction.
// ---------------------------------------------------------------------------
__global__ void finalize_rows_kernel(const int* __restrict__ labels) {
    int gw   = (blockIdx.x * blockDim.x + threadIdx.x) >> 5;
    int lane = threadIdx.x & 31;
    if (gw >= B) return;
    const float* pm = g_pmax + (size_t)gw * NTE;
    const float* ps = g_psum + (size_t)gw * NTE;

    float m = -INFINITY, s = 0.f;
    for (int t = lane; t < NTE; t += 32) {
        float mt = pm[t], st = ps[t];
        if (mt > m)      { s = s * __expf(m - mt) + st; m = mt; }
        else if (st > 0.f) s += st * __expf(mt - m);
    }
    #pragma unroll
    for (int o = 16; o > 0; o >>= 1) {
        float om = __shfl_xor_sync(0xffffffffu, m, o);
        float os = __shfl_xor_sync(0xffffffffu, s, o);
        float nm = fmaxf(m, om);
        float e1 = (s  > 0.f) ? __expf(m  - nm) : 0.f;
        float e2 = (os > 0.f) ? __expf(om - nm) : 0.f;
        s = s * e1 + os * e2;
        m = nm;
    }

    if (lane == 0) {
        int lab = labels[gw];
        float cosl = g_ldot[gw] * g_einv[gw] * g_winv[lab];
        float c2   = 1.0f - cosl * cosl;
        float sine = sqrtf(fminf(fmaxf(c2, 0.f), 1.f));
        float phi  = cosl * COS_M - sine * SIN_M;
        phi = (cosl > TH_M) ? phi : (cosl - MM_M);

        float lo = SCALE_F * cosl;   // original label logit
        float ln = SCALE_F * phi;    // margined logit (ln <= lo <= m)
        s += expf(ln - m) - expf(lo - m);
        g_nll[gw] = m + logf(s) - ln;
    }
}

__global__ void finalize_reduce_kernel(float* __restrict__ out) {
    __shared__ float red[B];
    int b = threadIdx.x;
    red[b] = g_nll[b];
    __syncthreads();
    #pragma unroll
    for (int o = B / 2; o > 0; o >>= 1) {
        if (b < o) red[b] += red[b + o];
        __syncthreads();
    }
    if (b == 0) out[0] = red[0] / (float)B;
}

// ---------------------------------------------------------------------------
extern "C" void kernel_launch(void* const* d_in, const int* in_sizes, int n_in,
                              void* d_out, int out_size) {
    const float* E      = (const float*)d_in[0];
    const float* W      = (const float*)d_in[1];
    const int*   labels = (const int*)d_in[2];
    float*       out    = (float*)d_out;

    cudaFuncSetAttribute(gemm_tc_kernel,
                         cudaFuncAttributeMaxDynamicSharedMemorySize, SMEM_BYTES);

    e_norm_kernel<<<(B * 32) / 256, 256>>>(E);
    w_norm_kernel<<<(C * 32 + 255) / 256, 256>>>(W);
    label_dot_kernel<<<(B * 32) / 256, 256>>>(E, W, labels);

    dim3 grid(B / TM, NT);   // (8, 782), x-major => W-tile L2 reuse
    gemm_tc_kernel<<<grid, 128, SMEM_BYTES>>>(E, W);

    finalize_rows_kernel<<<(B * 32 + 255) / 256, 256>>>(labels);
    finalize_reduce_kernel<<<1, B>>>(out);
}

// round 9
// speedup vs baseline: 6.1675x; 1.5794x over previous
#include <cuda_runtime.h>
#include <cuda_fp16.h>
#include <math.h>
#include <stdint.h>

// ---------------------------------------------------------------------------
// Problem constants
// ---------------------------------------------------------------------------
#define B       1024
#define D       512
#define C       100000
#define TM      128                    // CTA rows
#define TN      128                    // CTA classes
#define NT      ((C + TN - 1) / TN)    // 782 class tiles
#define NTE     (NT * 2)               // 2 col-half partials per class tile
#define KCHUNK  64                     // fp16 K elems per chunk (128B rows)
#define NCHUNK  (D / KCHUNK)           // 8
#define SCALE_F 64.0f
#define L2E_64  92.33248261689366f     // 64 * log2(e)

// ArcFace margin constants (margin = 0.5)
#define COS_M  0.8775825618903728f
#define SIN_M  0.47942553860420301f
#define TH_M  (-0.8775825618903728f)
#define MM_M   0.23971276930210151f

// smem: per stage A tile 128x128B (16KB) + B tile 128x128B (16KB)
#define TILE_BYTES  16384
#define STAGE_BYTES (2 * TILE_BYTES)
#define SMEM_BYTES  (1024 + 3 * STAGE_BYTES)   // 99328 -> 2 CTA/SM

// Scratch (__device__ globals; no allocations allowed)
__device__ __half g_Eh[(size_t)B * D];
__device__ __half g_Wh[(size_t)C * D];
__device__ float  g_einv[B];
__device__ float  g_winv[C];
__device__ float  g_ldot[B];
__device__ float  g_psum[(size_t)B * NTE];
__device__ float  g_nll[B];

// ---------------------------------------------------------------------------
// PTX helpers (base ISA only -- nothing gated on sm_103a)
// ---------------------------------------------------------------------------
__device__ __forceinline__ uint32_t smem_u32(const void* p) {
    uint32_t a;
    asm("{ .reg .u64 t; cvta.to.shared.u64 t, %1; cvt.u32.u64 %0, t; }"
        : "=r"(a) : "l"(p));
    return a;
}
__device__ __forceinline__ void cp16(uint32_t dst, const void* src) {
    asm volatile("cp.async.cg.shared.global [%0], [%1], 16;"
                 :: "r"(dst), "l"(src));
}
__device__ __forceinline__ void cp_commit() {
    asm volatile("cp.async.commit_group;" ::: "memory");
}
template <int N> __device__ __forceinline__ void cp_wait() {
    asm volatile("cp.async.wait_group %0;" :: "n"(N) : "memory");
}
__device__ __forceinline__ void st_zero16(uint32_t dst) {
    asm volatile("st.shared.v4.u32 [%0], {%1, %1, %1, %1};"
                 :: "r"(dst), "r"(0u) : "memory");
}
__device__ __forceinline__ void ldsm4(uint32_t* r, uint32_t addr) {
    asm volatile("ldmatrix.sync.aligned.m8n8.x4.shared.b16 {%0,%1,%2,%3}, [%4];"
                 : "=r"(r[0]), "=r"(r[1]), "=r"(r[2]), "=r"(r[3]) : "r"(addr));
}
__device__ __forceinline__ void mma_f16(float* d, const uint32_t* a,
                                        const uint32_t* b) {
    asm volatile(
        "mma.sync.aligned.m16n8k16.row.col.f32.f16.f16.f32 "
        "{%0,%1,%2,%3}, {%4,%5,%6,%7}, {%8,%9}, {%0,%1,%2,%3};"
        : "+f"(d[0]), "+f"(d[1]), "+f"(d[2]), "+f"(d[3])
        : "r"(a[0]), "r"(a[1]), "r"(a[2]), "r"(a[3]), "r"(b[0]), "r"(b[1]));
}
__device__ __forceinline__ float ex2(float x) {
    float r;
    asm("ex2.approx.ftz.f32 %0, %1;" : "=f"(r) : "f"(x));
    return r;
}

// ---------------------------------------------------------------------------
// Norm + fp16-convert kernels (one warp per row, fused single pass over data)
// ---------------------------------------------------------------------------
__global__ void e_conv_kernel(const float* __restrict__ E) {
    int warp = (blockIdx.x * blockDim.x + threadIdx.x) >> 5;
    int lane = threadIdx.x & 31;
    if (warp >= B) return;
    const float* row = E + (size_t)warp * D;
    __half2* dst = (__half2*)(g_Eh + (size_t)warp * D);
    float ss = 0.f;
    #pragma unroll
    for (int j = 0; j < 4; j++) {
        float4 v = *(const float4*)(row + (j * 32 + lane) * 4);
        ss = fmaf(v.x, v.x, fmaf(v.y, v.y, fmaf(v.z, v.z, fmaf(v.w, v.w, ss))));
        dst[(j * 32 + lane) * 2]     = __floats2half2_rn(v.x, v.y);
        dst[(j * 32 + lane) * 2 + 1] = __floats2half2_rn(v.z, v.w);
    }
    #pragma unroll
    for (int o = 16; o > 0; o >>= 1) ss += __shfl_xor_sync(0xffffffffu, ss, o);
    if (lane == 0) g_einv[warp] = 1.0f / fmaxf(sqrtf(ss), 1e-12f);
}

__global__ void w_conv_kernel(const float* __restrict__ W) {
    int warp = (blockIdx.x * blockDim.x + threadIdx.x) >> 5;
    int lane = threadIdx.x & 31;
    if (warp >= C) return;
    const float* row = W + (size_t)warp * D;
    __half2* dst = (__half2*)(g_Wh + (size_t)warp * D);
    float ss = 0.f;
    #pragma unroll
    for (int j = 0; j < 4; j++) {
        float4 v = *(const float4*)(row + (j * 32 + lane) * 4);
        ss = fmaf(v.x, v.x, fmaf(v.y, v.y, fmaf(v.z, v.z, fmaf(v.w, v.w, ss))));
        dst[(j * 32 + lane) * 2]     = __floats2half2_rn(v.x, v.y);
        dst[(j * 32 + lane) * 2 + 1] = __floats2half2_rn(v.z, v.w);
    }
    #pragma unroll
    for (int o = 16; o > 0; o >>= 1) ss += __shfl_xor_sync(0xffffffffu, ss, o);
    if (lane == 0) g_winv[warp] = 1.0f / fmaxf(sqrtf(ss), 1e-12f);
}

__global__ void label_dot_kernel(const float* __restrict__ E,
                                 const float* __restrict__ W,
                                 const int* __restrict__ labels) {
    int warp = (blockIdx.x * blockDim.x + threadIdx.x) >> 5;
    int lane = threadIdx.x & 31;
    if (warp >= B) return;
    int lab = labels[warp];
    const float* e = E + (size_t)warp * D;
    const float* w = W + (size_t)lab * D;
    float s = 0.f;
    #pragma unroll
    for (int i = 0; i < D / 32; i++) s = fmaf(e[lane + i * 32], w[lane + i * 32], s);
    #pragma unroll
    for (int o = 16; o > 0; o >>= 1) s += __shfl_xor_sync(0xffffffffu, s, o);
    if (lane == 0) g_ldot[warp] = s;
}

// ---------------------------------------------------------------------------
// Main: fp16 mma.sync GEMM (128x128 CTA, 4 warps of 64x64, ldmatrix, XOR
// swizzle) + fused fixed-max softmax partials (max == SCALE == 64).
// grid (8, 782) x-major: W tile HBM-read once, L2-hit by the other 7 rowTiles.
// ---------------------------------------------------------------------------
__global__ void __launch_bounds__(128, 2)
gemm_tc_kernel(void) {
    extern __shared__ float smem[];
    float* einv_s = smem;              // 128: einv * 64*log2e
    float* winv_s = smem + 128;        // 128
    char*  sdata  = (char*)(smem + 256);

    const int tid  = threadIdx.x;
    const int wid  = tid >> 5;
    const int lane = tid & 31;
    const int wm   = wid >> 1;
    const int wn   = wid & 1;
    const int qid  = lane >> 2;
    const int ql   = lane & 3;
    const int rowBase   = blockIdx.x * TM;
    const int classBase = blockIdx.y * TN;

    einv_s[tid] = g_einv[rowBase + tid] * L2E_64;
    winv_s[tid] = (classBase + tid < C) ? g_winv[classBase + tid] : 0.0f;

    float acc[4][8][4];
    #pragma unroll
    for (int mt = 0; mt < 4; mt++)
        #pragma unroll
        for (int nt = 0; nt < 8; nt++)
            #pragma unroll
            for (int c = 0; c < 4; c++) acc[mt][nt][c] = 0.f;

    const uint32_t s0 = smem_u32(sdata);

    // --- chunk loader: A 16KB + B 16KB, XOR-swizzled 16B units ---
    auto load_chunk = [&](int k, int st) {
        const uint32_t sa  = s0 + st * STAGE_BYTES;
        const uint32_t sb  = sa + TILE_BYTES;
        const int      kof = k * KCHUNK;
        const __half*  Ep  = g_Eh + (size_t)rowBase * D + kof;
        #pragma unroll
        for (int i = 0; i < 8; i++) {
            int idx = tid + i * 128;           // 0..1023
            int r = idx >> 3, c = idx & 7;
            uint32_t dst = sa + r * 128 + ((c ^ (r & 7)) << 4);
            cp16(dst, Ep + (size_t)r * D + c * 8);
        }
        #pragma unroll
        for (int i = 0; i < 8; i++) {
            int idx = tid + i * 128;
            int r = idx >> 3, c = idx & 7;
            int cls = classBase + r;
            uint32_t dst = sb + r * 128 + ((c ^ (r & 7)) << 4);
            if (cls < C) cp16(dst, g_Wh + (size_t)cls * D + kof + c * 8);
            else         st_zero16(dst);
        }
        cp_commit();
    };

    // ldmatrix per-lane address components
    const int aRow = (lane & 7) + ((lane >> 3) & 1) * 8;   // row within 16
    const int kgA  = lane >> 4;                            // k half
    const int bRow = (lane & 7) + (lane >> 4) * 8;         // row within 16
    const int kgB  = (lane >> 3) & 1;

    auto compute_chunk = [&](int st) {
        const uint32_t sa = s0 + st * STAGE_BYTES;
        const uint32_t sb = sa + TILE_BYTES;
        #pragma unroll
        for (int ks = 0; ks < 4; ks++) {
            uint32_t a[4][4], bb[4][4];
            const int cA = ks * 2 + kgA;
            const int cB = ks * 2 + kgB;
            const uint32_t swA = (uint32_t)((cA ^ (lane & 7)) << 4);
            const uint32_t swB = (uint32_t)((cB ^ (lane & 7)) << 4);
            #pragma unroll
            for (int mt = 0; mt < 4; mt++)
                ldsm4(a[mt], sa + (wm * 64 + mt * 16 + aRow) * 128 + swA);
            #pragma unroll
            for (int ntp = 0; ntp < 4; ntp++)
                ldsm4(bb[ntp], sb + (wn * 64 + ntp * 16 + bRow) * 128 + swB);
            #pragma unroll
            for (int mt = 0; mt < 4; mt++)
                #pragma unroll
                for (int nt = 0; nt < 8; nt++) {
                    uint32_t bfrag[2] = { bb[nt >> 1][(nt & 1) * 2],
                                          bb[nt >> 1][(nt & 1) * 2 + 1] };
                    mma_f16(acc[mt][nt], a[mt], bfrag);
                }
        }
    };

    load_chunk(0, 0);
    load_chunk(1, 1);
    load_chunk(2, 2);

    for (int k = 0; k < NCHUNK; k++) {
        const int st = k % 3;
        if (k < NCHUNK - 2)       cp_wait<2>();
        else if (k == NCHUNK - 2) cp_wait<1>();
        else                      cp_wait<0>();
        __syncthreads();
        compute_chunk(st);
        if (k + 3 < NCHUNK) {
            __syncthreads();              // all warps done reading stage st
            load_chunk(k + 3, st);
        }
    }

    // --- epilogue: partial Σ exp(l - 64), fixed max (l <= 64 always) ---
    const int tileIdx = blockIdx.y * 2 + wn;
    #pragma unroll
    for (int mt = 0; mt < 4; mt++) {
        #pragma unroll
        for (int h = 0; h < 2; h++) {
            const int   rloc = wm * 64 + mt * 16 + qid + h * 8;
            const float ew   = einv_s[rloc];
            float s = 0.f;
            #pragma unroll
            for (int nt = 0; nt < 8; nt++) {
                #pragma unroll
                for (int c = 0; c < 2; c++) {
                    float wv = winv_s[wn * 64 + nt * 8 + ql * 2 + c];
                    float u  = acc[mt][nt][h * 2 + c] * ew;
                    s += ex2(fmaf(u, wv, -L2E_64));
                }
            }
            s += __shfl_xor_sync(0xffffffffu, s, 1);
            s += __shfl_xor_sync(0xffffffffu, s, 2);
            if (ql == 0)
                g_psum[(size_t)(rowBase + rloc) * NTE + tileIdx] = s;
        }
    }
}

// ---------------------------------------------------------------------------
// Finalize stage 1: one warp per row sums NTE partials + label correction.
// ---------------------------------------------------------------------------
__global__ void finalize_rows_kernel(const int* __restrict__ labels) {
    int gw   = (blockIdx.x * blockDim.x + threadIdx.x) >> 5;
    int lane = threadIdx.x & 31;
    if (gw >= B) return;
    const float* ps = g_psum + (size_t)gw * NTE;

    float s = 0.f;
    for (int t = lane; t < NTE; t += 32) s += ps[t];
    #pragma unroll
    for (int o = 16; o > 0; o >>= 1) s += __shfl_xor_sync(0xffffffffu, s, o);

    if (lane == 0) {
        int lab = labels[gw];
        float cosl = g_ldot[gw] * g_einv[gw] * g_winv[lab];
        float c2   = 1.0f - cosl * cosl;
        float sine = sqrtf(fminf(fmaxf(c2, 0.f), 1.f));
        float phi  = cosl * COS_M - sine * SIN_M;
        phi = (cosl > TH_M) ? phi : (cosl - MM_M);

        float lo = SCALE_F * cosl;   // original label logit
        float ln = SCALE_F * phi;    // margined logit
        s += expf(ln - SCALE_F) - expf(lo - SCALE_F);
        // logZ = 64 + log(s); nll = logZ - ln
        g_nll[gw] = SCALE_F + logf(s) - ln;
    }
}

__global__ void finalize_reduce_kernel(float* __restrict__ out) {
    __shared__ float red[B];
    int b = threadIdx.x;
    red[b] = g_nll[b];
    __syncthreads();
    #pragma unroll
    for (int o = B / 2; o > 0; o >>= 1) {
        if (b < o) red[b] += red[b + o];
        __syncthreads();
    }
    if (b == 0) out[0] = red[0] / (float)B;
}

// ---------------------------------------------------------------------------
extern "C" void kernel_launch(void* const* d_in, const int* in_sizes, int n_in,
                              void* d_out, int out_size) {
    const float* E      = (const float*)d_in[0];
    const float* W      = (const float*)d_in[1];
    const int*   labels = (const int*)d_in[2];
    float*       out    = (float*)d_out;

    cudaFuncSetAttribute(gemm_tc_kernel,
                         cudaFuncAttributeMaxDynamicSharedMemorySize, SMEM_BYTES);

    e_conv_kernel<<<(B * 32) / 256, 256>>>(E);
    w_conv_kernel<<<(C * 32 + 255) / 256, 256>>>(W);
    label_dot_kernel<<<(B * 32) / 256, 256>>>(E, W, labels);

    dim3 grid(B / TM, NT);   // (8, 782), x-major => W-tile L2 reuse
    gemm_tc_kernel<<<grid, 128, SMEM_BYTES>>>();

    finalize_rows_kernel<<<(B * 32 + 255) / 256, 256>>>(labels);
    finalize_reduce_kernel<<<1, B>>>(out);
}